// round 14
// baseline (speedup 1.0000x reference)
#include <cuda_runtime.h>
#include <cuda_bf16.h>
#include <math.h>

#define Bb 32
#define Cc 512
#define Ff 512
#define Hh 4
#define Dk 128
#define NTOK (Bb*Cc)   // 16384

// ---------------- scratch (static device globals: allocation-free) ----------
__device__ float g_Q[Bb*Hh*Cc*Dk];
__device__ float g_K[Bb*Hh*Cc*Dk];
__device__ float g_V[Bb*Hh*Cc*Dk];
__device__ float g_att[NTOK*Ff];
__device__ float g_glob[NTOK*Ff];
__device__ float g_scr1[Ff*Ff];        // Wo1^T
__device__ float g_scr2[3*Ff*Ff];      // fused W'q2, W'k2, W'v2
__device__ float g_scr3[4*Ff];         // b'q2, b'k2, b'v2, zeros

// ======================= double-buffered fp32 SGEMM =========================
// C[M,512] = A[M,512] @ W[512,512]^T + bias ; headsplit: write [B,H,C,Dk]
__device__ __forceinline__ void sgemm_body(
    const float* __restrict__ A, const float* __restrict__ W,
    const float* __restrict__ bias, float* __restrict__ Cout, int headsplit,
    int m0, int n0)
{
    __shared__ float As[2][8][128];
    __shared__ float Bs[2][8][128];
    const int tid = threadIdx.x;
    const int lrow = tid >> 1, lseg = (tid & 1) * 4;
    const int tx = tid & 15, ty = tid >> 4;

    float acc[8][8];
#pragma unroll
    for (int i = 0; i < 8; i++)
#pragma unroll
        for (int j = 0; j < 8; j++) acc[i][j] = 0.f;

    const float* Ap = A + (size_t)(m0 + lrow) * 512 + lseg;
    const float* Wp = W + (size_t)(n0 + lrow) * 512 + lseg;

    float4 va = *(const float4*)Ap;
    float4 vb = *(const float4*)Wp;
    As[0][lseg+0][lrow]=va.x; As[0][lseg+1][lrow]=va.y;
    As[0][lseg+2][lrow]=va.z; As[0][lseg+3][lrow]=va.w;
    Bs[0][lseg+0][lrow]=vb.x; Bs[0][lseg+1][lrow]=vb.y;
    Bs[0][lseg+2][lrow]=vb.z; Bs[0][lseg+3][lrow]=vb.w;
    __syncthreads();

#pragma unroll 1
    for (int it = 0; it < 63; it++) {
        const int kt = 8 + it * 8;
        va = *(const float4*)(Ap + kt);
        vb = *(const float4*)(Wp + kt);
        const int cur = it & 1;
#pragma unroll
        for (int k = 0; k < 8; k++) {
            float4 a0 = *(const float4*)&As[cur][k][ty*8];
            float4 a1 = *(const float4*)&As[cur][k][ty*8+4];
            float4 b0 = *(const float4*)&Bs[cur][k][tx*8];
            float4 b1 = *(const float4*)&Bs[cur][k][tx*8+4];
            float av[8] = {a0.x,a0.y,a0.z,a0.w,a1.x,a1.y,a1.z,a1.w};
            float bv[8] = {b0.x,b0.y,b0.z,b0.w,b1.x,b1.y,b1.z,b1.w};
#pragma unroll
            for (int i = 0; i < 8; i++)
#pragma unroll
                for (int j = 0; j < 8; j++)
                    acc[i][j] += av[i]*bv[j];
        }
        const int nxt = cur ^ 1;
        As[nxt][lseg+0][lrow]=va.x; As[nxt][lseg+1][lrow]=va.y;
        As[nxt][lseg+2][lrow]=va.z; As[nxt][lseg+3][lrow]=va.w;
        Bs[nxt][lseg+0][lrow]=vb.x; Bs[nxt][lseg+1][lrow]=vb.y;
        Bs[nxt][lseg+2][lrow]=vb.z; Bs[nxt][lseg+3][lrow]=vb.w;
        __syncthreads();
    }
    {
#pragma unroll
        for (int k = 0; k < 8; k++) {
            float4 a0 = *(const float4*)&As[1][k][ty*8];
            float4 a1 = *(const float4*)&As[1][k][ty*8+4];
            float4 b0 = *(const float4*)&Bs[1][k][tx*8];
            float4 b1 = *(const float4*)&Bs[1][k][tx*8+4];
            float av[8] = {a0.x,a0.y,a0.z,a0.w,a1.x,a1.y,a1.z,a1.w};
            float bv[8] = {b0.x,b0.y,b0.z,b0.w,b1.x,b1.y,b1.z,b1.w};
#pragma unroll
            for (int i = 0; i < 8; i++)
#pragma unroll
                for (int j = 0; j < 8; j++)
                    acc[i][j] += av[i]*bv[j];
        }
    }

#pragma unroll
    for (int i = 0; i < 8; i++) {
        int m = m0 + ty*8 + i;
        int bidx = m >> 9, cidx = m & 511;
#pragma unroll
        for (int j = 0; j < 8; j++) {
            int n = n0 + tx*8 + j;
            float v = acc[i][j] + bias[n];
            if (headsplit) {
                int hh = n >> 7, dd = n & 127;
                Cout[((size_t)((bidx*Hh + hh)*Cc + cidx))*Dk + dd] = v;
            } else {
                Cout[(size_t)m*Ff + n] = v;
            }
        }
    }
}

__global__ __launch_bounds__(256) void sgemm_nt_kernel(
    const float* __restrict__ A, const float* __restrict__ W,
    const float* __restrict__ bias, float* __restrict__ Cout, int headsplit)
{
    sgemm_body(A, W, bias, Cout, headsplit, blockIdx.y*128, blockIdx.x*128);
}

__global__ __launch_bounds__(256) void sgemm_qkv_kernel(
    const float* __restrict__ A,
    const float* __restrict__ W0, const float* __restrict__ b0, float* __restrict__ C0,
    const float* __restrict__ W1, const float* __restrict__ b1, float* __restrict__ C1,
    const float* __restrict__ W2, const float* __restrict__ b2, float* __restrict__ C2)
{
    const float* W = W0; const float* bi = b0; float* C = C0;
    if (blockIdx.z == 1) { W = W1; bi = b1; C = C1; }
    else if (blockIdx.z == 2) { W = W2; bi = b2; C = C2; }
    sgemm_body(A, W, bi, C, 1, blockIdx.y*128, blockIdx.x*128);
}

// fused-weight prep: C_z = A_z @ Wo1T^T  (i.e., W'_z[n][k] = sum_j Wz[n][j]Wo1[j][k])
__global__ __launch_bounds__(256) void sgemm_fuse_kernel(
    const float* __restrict__ Wq2, const float* __restrict__ Wk2,
    const float* __restrict__ Wv2, const float* __restrict__ Wo1T,
    const float* __restrict__ zeros,
    float* __restrict__ Cq, float* __restrict__ Ck, float* __restrict__ Cv)
{
    const float* A = Wq2; float* C = Cq;
    if (blockIdx.z == 1) { A = Wk2; C = Ck; }
    else if (blockIdx.z == 2) { A = Wv2; C = Cv; }
    sgemm_body(A, Wo1T, zeros, C, 0, blockIdx.y*128, blockIdx.x*128);
}

// ======================= 512x512 transpose ==================================
__global__ __launch_bounds__(256) void transpose512_kernel(
    const float* __restrict__ in, float* __restrict__ out)
{
    __shared__ float t[32][33];
    const int tx = threadIdx.x, ty = threadIdx.y;   // (32, 8)
    const int x0 = blockIdx.x*32, y0 = blockIdx.y*32;
#pragma unroll
    for (int r = 0; r < 4; r++)
        t[ty*4+r][tx] = in[(size_t)(y0 + ty*4 + r)*512 + x0 + tx];
    __syncthreads();
#pragma unroll
    for (int r = 0; r < 4; r++)
        out[(size_t)(x0 + ty*4 + r)*512 + y0 + tx] = t[tx][ty*4+r];
}

// ======================= bias fusion + zeros ================================
// b'_z[i] = sum_m Wz[i][m]*bo1[m] + bz[i];  also zeroes the zeros[] array.
__global__ __launch_bounds__(256) void biasfuse_kernel(
    const float* __restrict__ Wq2, const float* __restrict__ Wk2,
    const float* __restrict__ Wv2, const float* __restrict__ bo1,
    const float* __restrict__ bq2, const float* __restrict__ bk2,
    const float* __restrict__ bv2,
    float* __restrict__ bpq, float* __restrict__ bpk, float* __restrict__ bpv,
    float* __restrict__ zeros)
{
    const int z = blockIdx.x;
    const float* W = (z == 0) ? Wq2 : (z == 1) ? Wk2 : Wv2;
    const float* bi = (z == 0) ? bq2 : (z == 1) ? bk2 : bv2;
    float* bo = (z == 0) ? bpq : (z == 1) ? bpk : bpv;
    const int wid = threadIdx.x >> 5, lane = threadIdx.x & 31;

    if (z == 0) { zeros[threadIdx.x] = 0.f; zeros[threadIdx.x + 256] = 0.f; }

    for (int i = wid; i < 512; i += 8) {
        const float* row = W + (size_t)i * 512;
        float s = 0.f;
#pragma unroll
        for (int seg = 0; seg < 16; seg++)
            s += row[lane + seg*32] * bo1[lane + seg*32];
#pragma unroll
        for (int o = 16; o; o >>= 1)
            s += __shfl_xor_sync(0xffffffffu, s, o);
        if (lane == 0) bo[i] = s + bi[i];
    }
}

// ======================= top-5 insertion helper =============================
__device__ __forceinline__ void ins5(float (&v)[5], int (&ix)[5], float sv, int id)
{
    if (sv > v[4]) {
        if (sv > v[0]) {
            v[4]=v[3]; ix[4]=ix[3]; v[3]=v[2]; ix[3]=ix[2];
            v[2]=v[1]; ix[2]=ix[1]; v[1]=v[0]; ix[1]=ix[0];
            v[0]=sv; ix[0]=id;
        } else if (sv > v[1]) {
            v[4]=v[3]; ix[4]=ix[3]; v[3]=v[2]; ix[3]=ix[2];
            v[2]=v[1]; ix[2]=ix[1]; v[1]=sv; ix[1]=id;
        } else if (sv > v[2]) {
            v[4]=v[3]; ix[4]=ix[3]; v[3]=v[2]; ix[3]=ix[2];
            v[2]=sv; ix[2]=id;
        } else if (sv > v[3]) {
            v[4]=v[3]; ix[4]=ix[3]; v[3]=sv; ix[3]=id;
        } else {
            v[4]=sv; ix[4]=id;
        }
    }
}

// ======================= Stage-1: top-5 local attention =====================
#define LOC_SMEM_FLOATS (32*129 + 128*129 + 32*5 + 32*5)
#define LOC_SMEM_BYTES  (LOC_SMEM_FLOATS*4)

__global__ __launch_bounds__(256) void local_attn_kernel(
    const float* __restrict__ Q, const float* __restrict__ K,
    const float* __restrict__ V, float* __restrict__ out)
{
    extern __shared__ float sm[];
    float* Qs = sm;
    float* Ks = Qs + 32*129;
    float* w5 = Ks + 128*129;
    int*   i5 = (int*)(w5 + 32*5);
    float* cvals = Ks;
    int*   cidx  = (int*)(Ks + 32*160);

    const int tid = threadIdx.x;
    const int b = blockIdx.z, h = blockIdx.y;
    const int q0 = blockIdx.x * 32;
    const float* Qb = Q + (size_t)((b*Hh + h)*Cc) * Dk;
    const float* Kb = K + (size_t)((b*Hh + h)*Cc) * Dk;
    const float* Vb = V + (size_t)((b*Hh + h)*Cc) * Dk;

    for (int t = tid; t < 32*32; t += 256) {
        int row = t >> 5, seg = t & 31;
        float4 v = ((const float4*)(Qb + (size_t)(q0 + row)*Dk))[seg];
        float* p = Qs + row*129 + seg*4;
        p[0]=v.x; p[1]=v.y; p[2]=v.z; p[3]=v.w;
    }

    const int qg = tid >> 5;
    const int lane = tid & 31;
    const float scl = 0.08838834764831845f;

    float tv[4][5]; int ti[4][5];
#pragma unroll
    for (int r = 0; r < 4; r++)
#pragma unroll
        for (int j = 0; j < 5; j++) { tv[r][j] = -1e30f; ti[r][j] = 0; }

    for (int ch = 0; ch < 4; ch++) {
        const int e0 = ch * 128;
        for (int t = tid; t < 128*32; t += 256) {
            int row = t >> 5, seg = t & 31;
            float4 v = ((const float4*)(Kb + (size_t)(e0 + row)*Dk))[seg];
            float* p = Ks + row*129 + seg*4;
            p[0]=v.x; p[1]=v.y; p[2]=v.z; p[3]=v.w;
        }
        __syncthreads();

        float a[4][4];
#pragma unroll
        for (int r = 0; r < 4; r++)
#pragma unroll
            for (int j = 0; j < 4; j++) a[r][j] = 0.f;

        const float* qp  = Qs + (qg*4)*129;
        const float* kp0 = Ks + lane*129;
        const float* kp1 = kp0 + 32*129;
        const float* kp2 = kp0 + 64*129;
        const float* kp3 = kp0 + 96*129;
#pragma unroll 4
        for (int k = 0; k < 128; k++) {
            float qv0 = qp[k], qv1 = qp[129+k], qv2 = qp[258+k], qv3 = qp[387+k];
            float kv0 = kp0[k], kv1 = kp1[k], kv2 = kp2[k], kv3 = kp3[k];
            a[0][0]+=qv0*kv0; a[0][1]+=qv0*kv1; a[0][2]+=qv0*kv2; a[0][3]+=qv0*kv3;
            a[1][0]+=qv1*kv0; a[1][1]+=qv1*kv1; a[1][2]+=qv1*kv2; a[1][3]+=qv1*kv3;
            a[2][0]+=qv2*kv0; a[2][1]+=qv2*kv1; a[2][2]+=qv2*kv2; a[2][3]+=qv2*kv3;
            a[3][0]+=qv3*kv0; a[3][1]+=qv3*kv1; a[3][2]+=qv3*kv2; a[3][3]+=qv3*kv3;
        }
#pragma unroll
        for (int r = 0; r < 4; r++)
#pragma unroll
            for (int j = 0; j < 4; j++)
                ins5(tv[r], ti[r], a[r][j]*scl, e0 + lane + 32*j);
        __syncthreads();
    }

#pragma unroll
    for (int r = 0; r < 4; r++) {
        int row = qg*4 + r;
#pragma unroll
        for (int j = 0; j < 5; j++) {
            cvals[row*160 + lane*5 + j] = tv[r][j];
            cidx [row*160 + lane*5 + j] = ti[r][j];
        }
    }
    __syncthreads();

    if (tid < 32) {
        float v[5]; int ix[5];
#pragma unroll
        for (int j = 0; j < 5; j++) { v[j] = -1e30f; ix[j] = 0; }
        const float* cv = cvals + tid*160;
        const int*   ci = cidx  + tid*160;
        for (int j = 0; j < 160; j++) ins5(v, ix, cv[j], ci[j]);
        float m = v[0];
        float w0 = 1.f;
        float w1 = __expf(v[1]-m), w2 = __expf(v[2]-m);
        float w3 = __expf(v[3]-m), w4 = __expf(v[4]-m);
        float inv = 1.f / (w0+w1+w2+w3+w4);
        w5[tid*5+0]=w0*inv; w5[tid*5+1]=w1*inv; w5[tid*5+2]=w2*inv;
        w5[tid*5+3]=w3*inv; w5[tid*5+4]=w4*inv;
        i5[tid*5+0]=ix[0]; i5[tid*5+1]=ix[1]; i5[tid*5+2]=ix[2];
        i5[tid*5+3]=ix[3]; i5[tid*5+4]=ix[4];
    }
    __syncthreads();

    const int q  = tid >> 3;
    const int d0 = (tid & 7) * 16;
    float acc[16];
#pragma unroll
    for (int t = 0; t < 16; t++) acc[t] = 0.f;
#pragma unroll
    for (int j = 0; j < 5; j++) {
        float w = w5[q*5+j];
        int   e = i5[q*5+j];
        const float4* vr = (const float4*)(Vb + (size_t)e*Dk + d0);
#pragma unroll
        for (int t = 0; t < 4; t++) {
            float4 v = vr[t];
            acc[t*4+0] += w*v.x; acc[t*4+1] += w*v.y;
            acc[t*4+2] += w*v.z; acc[t*4+3] += w*v.w;
        }
    }
    float* op = out + (size_t)(b*Cc + q0 + q)*Ff + h*Dk + d0;
#pragma unroll
    for (int t = 0; t < 4; t++)
        ((float4*)op)[t] = make_float4(acc[t*4+0],acc[t*4+1],acc[t*4+2],acc[t*4+3]);
}

// ======================= Stage-2: flash global attention ====================
#define GLB_SMEM_FLOATS (32*129 + 128*129 + 32*132)
#define GLB_SMEM_BYTES  (GLB_SMEM_FLOATS*4)

__global__ __launch_bounds__(256) void global_attn_kernel(
    const float* __restrict__ Q, const float* __restrict__ K,
    const float* __restrict__ V, float* __restrict__ out)
{
    extern __shared__ float sm[];
    float* Qs = sm;
    float* KV = Qs + 32*129;
    float* sw = KV + 128*129;

    const int tid = threadIdx.x;
    const int b = blockIdx.z, h = blockIdx.y;
    const int q0 = blockIdx.x * 32;
    const float* Qb = Q + (size_t)((b*Hh + h)*Cc) * Dk;
    const float* Kb = K + (size_t)((b*Hh + h)*Cc) * Dk;
    const float* Vb = V + (size_t)((b*Hh + h)*Cc) * Dk;

    for (int t = tid; t < 32*32; t += 256) {
        int row = t >> 5, seg = t & 31;
        float4 v = ((const float4*)(Qb + (size_t)(q0 + row)*Dk))[seg];
        float* p = Qs + row*129 + seg*4;
        p[0]=v.x; p[1]=v.y; p[2]=v.z; p[3]=v.w;
    }

    const int qg = tid >> 5;
    const int lane = tid & 31;
    const float scl = 0.08838834764831845f;

    float acc[4][4];
    float mrun[4], lrun[4];
#pragma unroll
    for (int r = 0; r < 4; r++) {
        mrun[r] = -1e30f; lrun[r] = 0.f;
#pragma unroll
        for (int j = 0; j < 4; j++) acc[r][j] = 0.f;
    }

    for (int ch = 0; ch < 4; ch++) {
        const int e0 = ch * 128;
        for (int t = tid; t < 128*32; t += 256) {
            int row = t >> 5, seg = t & 31;
            float4 v = ((const float4*)(Kb + (size_t)(e0 + row)*Dk))[seg];
            float* p = KV + row*129 + seg*4;
            p[0]=v.x; p[1]=v.y; p[2]=v.z; p[3]=v.w;
        }
        __syncthreads();

        float a[4][4];
#pragma unroll
        for (int r = 0; r < 4; r++)
#pragma unroll
            for (int j = 0; j < 4; j++) a[r][j] = 0.f;

        const float* qp  = Qs + (qg*4)*129;
        const float* kp0 = KV + lane*129;
        const float* kp1 = kp0 + 32*129;
        const float* kp2 = kp0 + 64*129;
        const float* kp3 = kp0 + 96*129;
#pragma unroll 4
        for (int k = 0; k < 128; k++) {
            float qv0 = qp[k], qv1 = qp[129+k], qv2 = qp[258+k], qv3 = qp[387+k];
            float kv0 = kp0[k], kv1 = kp1[k], kv2 = kp2[k], kv3 = kp3[k];
            a[0][0]+=qv0*kv0; a[0][1]+=qv0*kv1; a[0][2]+=qv0*kv2; a[0][3]+=qv0*kv3;
            a[1][0]+=qv1*kv0; a[1][1]+=qv1*kv1; a[1][2]+=qv1*kv2; a[1][3]+=qv1*kv3;
            a[2][0]+=qv2*kv0; a[2][1]+=qv2*kv1; a[2][2]+=qv2*kv2; a[2][3]+=qv2*kv3;
            a[3][0]+=qv3*kv0; a[3][1]+=qv3*kv1; a[3][2]+=qv3*kv2; a[3][3]+=qv3*kv3;
        }

#pragma unroll
        for (int r = 0; r < 4; r++) {
            float s0 = a[r][0]*scl, s1 = a[r][1]*scl, s2 = a[r][2]*scl, s3 = a[r][3]*scl;
            float cm = fmaxf(fmaxf(s0,s1), fmaxf(s2,s3));
#pragma unroll
            for (int o = 16; o; o >>= 1)
                cm = fmaxf(cm, __shfl_xor_sync(0xffffffffu, cm, o));
            float mnew = fmaxf(mrun[r], cm);
            float corr = __expf(mrun[r] - mnew);
            float p0 = __expf(s0 - mnew), p1 = __expf(s1 - mnew);
            float p2 = __expf(s2 - mnew), p3 = __expf(s3 - mnew);
            float ps = p0+p1+p2+p3;
#pragma unroll
            for (int o = 16; o; o >>= 1)
                ps += __shfl_xor_sync(0xffffffffu, ps, o);
            lrun[r] = lrun[r]*corr + ps;
            mrun[r] = mnew;
            acc[r][0]*=corr; acc[r][1]*=corr; acc[r][2]*=corr; acc[r][3]*=corr;
            float* swr = sw + (qg*4 + r)*132;
            swr[lane]      = p0;
            swr[lane + 32] = p1;
            swr[lane + 64] = p2;
            swr[lane + 96] = p3;
        }
        __syncthreads();

        for (int t = tid; t < 128*32; t += 256) {
            int row = t >> 5, seg = t & 31;
            float4 v = ((const float4*)(Vb + (size_t)(e0 + row)*Dk))[seg];
            float* p = KV + row*129 + seg*4;
            p[0]=v.x; p[1]=v.y; p[2]=v.z; p[3]=v.w;
        }
        __syncthreads();

        {
            const float* swr0 = sw + (qg*4+0)*132;
            const float* swr1 = sw + (qg*4+1)*132;
            const float* swr2 = sw + (qg*4+2)*132;
            const float* swr3 = sw + (qg*4+3)*132;
#pragma unroll 8
            for (int e = 0; e < 128; e++) {
                float w0 = swr0[e], w1 = swr1[e], w2 = swr2[e], w3 = swr3[e];
                const float* vp = KV + e*129 + lane;
                float v0 = vp[0], v1 = vp[32], v2 = vp[64], v3 = vp[96];
                acc[0][0]+=w0*v0; acc[0][1]+=w0*v1; acc[0][2]+=w0*v2; acc[0][3]+=w0*v3;
                acc[1][0]+=w1*v0; acc[1][1]+=w1*v1; acc[1][2]+=w1*v2; acc[1][3]+=w1*v3;
                acc[2][0]+=w2*v0; acc[2][1]+=w2*v1; acc[2][2]+=w2*v2; acc[2][3]+=w2*v3;
                acc[3][0]+=w3*v0; acc[3][1]+=w3*v1; acc[3][2]+=w3*v2; acc[3][3]+=w3*v3;
            }
        }
        __syncthreads();
    }

#pragma unroll
    for (int r = 0; r < 4; r++) {
        float inv = 1.f / lrun[r];
        int row = q0 + qg*4 + r;
        float* base = out + (size_t)(b*Cc + row)*Ff + h*Dk;
        base[lane]      = acc[r][0]*inv;
        base[lane + 32] = acc[r][1]*inv;
        base[lane + 64] = acc[r][2]*inv;
        base[lane + 96] = acc[r][3]*inv;
    }
}

// ======================= residual + LayerNorm ===============================
__global__ __launch_bounds__(128) void resid_ln_kernel(
    const float* __restrict__ x, const float* __restrict__ gl,
    const float* __restrict__ gamma, const float* __restrict__ beta,
    float* __restrict__ out)
{
    __shared__ float s1[4], s2[4];
    const int row = blockIdx.x, tid = threadIdx.x;
    const float4 xv = ((const float4*)(x  + (size_t)row*Ff))[tid];
    const float4 gv = ((const float4*)(gl + (size_t)row*Ff))[tid];
    float h0 = xv.x+gv.x, h1 = xv.y+gv.y, h2 = xv.z+gv.z, h3 = xv.w+gv.w;
    float s = h0+h1+h2+h3;
    float q = h0*h0+h1*h1+h2*h2+h3*h3;
#pragma unroll
    for (int o = 16; o; o >>= 1) {
        s += __shfl_xor_sync(0xffffffffu, s, o);
        q += __shfl_xor_sync(0xffffffffu, q, o);
    }
    int w = tid >> 5;
    if ((tid & 31) == 0) { s1[w] = s; s2[w] = q; }
    __syncthreads();
    float ts = s1[0]+s1[1]+s1[2]+s1[3];
    float tq = s2[0]+s2[1]+s2[2]+s2[3];
    float mean = ts * (1.f/512.f);
    float var  = tq * (1.f/512.f) - mean*mean;
    float inv  = rsqrtf(var + 1e-5f);
    const float4 gm = ((const float4*)gamma)[tid];
    const float4 bt = ((const float4*)beta)[tid];
    float4 o;
    o.x = (h0-mean)*inv*gm.x + bt.x;
    o.y = (h1-mean)*inv*gm.y + bt.y;
    o.z = (h2-mean)*inv*gm.z + bt.z;
    o.w = (h3-mean)*inv*gm.w + bt.w;
    ((float4*)(out + (size_t)row*Ff))[tid] = o;
}

// ============================================================================
extern "C" void kernel_launch(void* const* d_in, const int* in_sizes, int n_in,
                              void* d_out, int out_size)
{
    const float* x    = (const float*)d_in[0];
    const float* Wq1  = (const float*)d_in[1];
    const float* bq1  = (const float*)d_in[2];
    const float* Wk1  = (const float*)d_in[3];
    const float* bk1  = (const float*)d_in[4];
    const float* Wv1  = (const float*)d_in[5];
    const float* bv1  = (const float*)d_in[6];
    const float* Wo1  = (const float*)d_in[7];
    const float* bo1  = (const float*)d_in[8];
    const float* Wq2  = (const float*)d_in[9];
    const float* bq2  = (const float*)d_in[10];
    const float* Wk2  = (const float*)d_in[11];
    const float* bk2  = (const float*)d_in[12];
    const float* Wv2  = (const float*)d_in[13];
    const float* bv2  = (const float*)d_in[14];
    const float* Wo2  = (const float*)d_in[15];
    const float* bo2  = (const float*)d_in[16];
    const float* gamma= (const float*)d_in[17];
    const float* beta = (const float*)d_in[18];
    float* out = (float*)d_out;

    float *Qp, *Kp, *Vp, *attp, *globp, *wo1t, *wfused, *bfused;
    cudaGetSymbolAddress((void**)&Qp,     g_Q);
    cudaGetSymbolAddress((void**)&Kp,     g_K);
    cudaGetSymbolAddress((void**)&Vp,     g_V);
    cudaGetSymbolAddress((void**)&attp,   g_att);
    cudaGetSymbolAddress((void**)&globp,  g_glob);
    cudaGetSymbolAddress((void**)&wo1t,   g_scr1);
    cudaGetSymbolAddress((void**)&wfused, g_scr2);
    cudaGetSymbolAddress((void**)&bfused, g_scr3);

    float* Wpq = wfused;
    float* Wpk = wfused + Ff*Ff;
    float* Wpv = wfused + 2*Ff*Ff;
    float* bpq = bfused;
    float* bpk = bfused + Ff;
    float* bpv = bfused + 2*Ff;
    float* zeros = bfused + 3*Ff;

    cudaFuncSetAttribute(local_attn_kernel,
        cudaFuncAttributeMaxDynamicSharedMemorySize, LOC_SMEM_BYTES);
    cudaFuncSetAttribute(global_attn_kernel,
        cudaFuncAttributeMaxDynamicSharedMemorySize, GLB_SMEM_BYTES);

    dim3 ggrid(4, 128);
    dim3 qkvgrid(4, 128, 3);
    dim3 fusegrid(4, 4, 3);
    dim3 tgrid(16, 16);
    dim3 tblk(32, 8);
    dim3 agrid(16, 4, 32);

    // ---- per-call prep: fold O1 into stage-2 projections ----
    transpose512_kernel<<<tgrid, tblk>>>(Wo1, wo1t);
    biasfuse_kernel<<<3, 256>>>(Wq2, Wk2, Wv2, bo1, bq2, bk2, bv2,
                                bpq, bpk, bpv, zeros);
    sgemm_fuse_kernel<<<fusegrid, 256>>>(Wq2, Wk2, Wv2, wo1t, zeros,
                                         Wpq, Wpk, Wpv);

    // Stage 1: fused Q/K/V projections (head-split)
    sgemm_qkv_kernel<<<qkvgrid, 256>>>(x, Wq1, bq1, Qp, Wk1, bk1, Kp, Wv1, bv1, Vp);
    // Top-5 local attention -> merged layout (att1)
    local_attn_kernel<<<agrid, 256, LOC_SMEM_BYTES>>>(Qp, Kp, Vp, attp);
    // Stage 2: fused projections directly on att1 (O1 eliminated)
    sgemm_qkv_kernel<<<qkvgrid, 256>>>(attp, Wpq, bpq, Qp, Wpk, bpk, Kp, Wpv, bpv, Vp);
    // Dense global attention (flash online softmax)
    global_attn_kernel<<<agrid, 256, GLB_SMEM_BYTES>>>(Qp, Kp, Vp, attp);
    // Output projection
    sgemm_nt_kernel<<<ggrid, 256>>>(attp, Wo2, bo2, globp, 0);
    // Residual + LayerNorm -> final output
    resid_ln_kernel<<<NTOK, 128>>>(x, globp, gamma, beta, out);
}

// round 15
// speedup vs baseline: 1.0026x; 1.0026x over previous
#include <cuda_runtime.h>
#include <cuda_bf16.h>
#include <math.h>

#define Bb 32
#define Cc 512
#define Ff 512
#define Hh 4
#define Dk 128
#define NTOK (Bb*Cc)   // 16384

// ---------------- scratch (static device globals: allocation-free) ----------
__device__ float g_Q[Bb*Hh*Cc*Dk];
__device__ float g_K[Bb*Hh*Cc*Dk];
__device__ float g_V[Bb*Hh*Cc*Dk];
__device__ float g_att[NTOK*Ff];
__device__ float g_glob[NTOK*Ff];
__device__ float g_scr1[Ff*Ff];        // Wo1^T
__device__ float g_scr2[3*Ff*Ff];      // fused W'q2, W'k2, W'v2
__device__ float g_scr3[4*Ff];         // b'q2, b'k2, b'v2, zeros

// ======================= double-buffered fp32 SGEMM =========================
// C[M,512] = A[M,512] @ W[512,512]^T + bias ; headsplit: write [B,H,C,Dk]
__device__ __forceinline__ void sgemm_body(
    const float* __restrict__ A, const float* __restrict__ W,
    const float* __restrict__ bias, float* __restrict__ Cout, int headsplit,
    int m0, int n0)
{
    __shared__ float As[2][8][128];
    __shared__ float Bs[2][8][128];
    const int tid = threadIdx.x;
    const int lrow = tid >> 1, lseg = (tid & 1) * 4;
    const int tx = tid & 15, ty = tid >> 4;

    float acc[8][8];
#pragma unroll
    for (int i = 0; i < 8; i++)
#pragma unroll
        for (int j = 0; j < 8; j++) acc[i][j] = 0.f;

    const float* Ap = A + (size_t)(m0 + lrow) * 512 + lseg;
    const float* Wp = W + (size_t)(n0 + lrow) * 512 + lseg;

    float4 va = *(const float4*)Ap;
    float4 vb = *(const float4*)Wp;
    As[0][lseg+0][lrow]=va.x; As[0][lseg+1][lrow]=va.y;
    As[0][lseg+2][lrow]=va.z; As[0][lseg+3][lrow]=va.w;
    Bs[0][lseg+0][lrow]=vb.x; Bs[0][lseg+1][lrow]=vb.y;
    Bs[0][lseg+2][lrow]=vb.z; Bs[0][lseg+3][lrow]=vb.w;
    __syncthreads();

#pragma unroll 1
    for (int it = 0; it < 63; it++) {
        const int kt = 8 + it * 8;
        va = *(const float4*)(Ap + kt);
        vb = *(const float4*)(Wp + kt);
        const int cur = it & 1;
#pragma unroll
        for (int k = 0; k < 8; k++) {
            float4 a0 = *(const float4*)&As[cur][k][ty*8];
            float4 a1 = *(const float4*)&As[cur][k][ty*8+4];
            float4 b0 = *(const float4*)&Bs[cur][k][tx*8];
            float4 b1 = *(const float4*)&Bs[cur][k][tx*8+4];
            float av[8] = {a0.x,a0.y,a0.z,a0.w,a1.x,a1.y,a1.z,a1.w};
            float bv[8] = {b0.x,b0.y,b0.z,b0.w,b1.x,b1.y,b1.z,b1.w};
#pragma unroll
            for (int i = 0; i < 8; i++)
#pragma unroll
                for (int j = 0; j < 8; j++)
                    acc[i][j] += av[i]*bv[j];
        }
        const int nxt = cur ^ 1;
        As[nxt][lseg+0][lrow]=va.x; As[nxt][lseg+1][lrow]=va.y;
        As[nxt][lseg+2][lrow]=va.z; As[nxt][lseg+3][lrow]=va.w;
        Bs[nxt][lseg+0][lrow]=vb.x; Bs[nxt][lseg+1][lrow]=vb.y;
        Bs[nxt][lseg+2][lrow]=vb.z; Bs[nxt][lseg+3][lrow]=vb.w;
        __syncthreads();
    }
    {
#pragma unroll
        for (int k = 0; k < 8; k++) {
            float4 a0 = *(const float4*)&As[1][k][ty*8];
            float4 a1 = *(const float4*)&As[1][k][ty*8+4];
            float4 b0 = *(const float4*)&Bs[1][k][tx*8];
            float4 b1 = *(const float4*)&Bs[1][k][tx*8+4];
            float av[8] = {a0.x,a0.y,a0.z,a0.w,a1.x,a1.y,a1.z,a1.w};
            float bv[8] = {b0.x,b0.y,b0.z,b0.w,b1.x,b1.y,b1.z,b1.w};
#pragma unroll
            for (int i = 0; i < 8; i++)
#pragma unroll
                for (int j = 0; j < 8; j++)
                    acc[i][j] += av[i]*bv[j];
        }
    }

#pragma unroll
    for (int i = 0; i < 8; i++) {
        int m = m0 + ty*8 + i;
        int bidx = m >> 9, cidx = m & 511;
#pragma unroll
        for (int j = 0; j < 8; j++) {
            int n = n0 + tx*8 + j;
            float v = acc[i][j] + bias[n];
            if (headsplit) {
                int hh = n >> 7, dd = n & 127;
                Cout[((size_t)((bidx*Hh + hh)*Cc + cidx))*Dk + dd] = v;
            } else {
                Cout[(size_t)m*Ff + n] = v;
            }
        }
    }
}

__global__ __launch_bounds__(256) void sgemm_nt_kernel(
    const float* __restrict__ A, const float* __restrict__ W,
    const float* __restrict__ bias, float* __restrict__ Cout, int headsplit)
{
    sgemm_body(A, W, bias, Cout, headsplit, blockIdx.y*128, blockIdx.x*128);
}

__global__ __launch_bounds__(256) void sgemm_qkv_kernel(
    const float* __restrict__ A,
    const float* __restrict__ W0, const float* __restrict__ b0, float* __restrict__ C0,
    const float* __restrict__ W1, const float* __restrict__ b1, float* __restrict__ C1,
    const float* __restrict__ W2, const float* __restrict__ b2, float* __restrict__ C2)
{
    const float* W = W0; const float* bi = b0; float* C = C0;
    if (blockIdx.z == 1) { W = W1; bi = b1; C = C1; }
    else if (blockIdx.z == 2) { W = W2; bi = b2; C = C2; }
    sgemm_body(A, W, bi, C, 1, blockIdx.y*128, blockIdx.x*128);
}

// fused-weight prep: C_z = A_z @ Wo1T^T  (i.e., W'_z[n][k] = sum_j Wz[n][j]Wo1[j][k])
__global__ __launch_bounds__(256) void sgemm_fuse_kernel(
    const float* __restrict__ Wq2, const float* __restrict__ Wk2,
    const float* __restrict__ Wv2, const float* __restrict__ Wo1T,
    const float* __restrict__ zeros,
    float* __restrict__ Cq, float* __restrict__ Ck, float* __restrict__ Cv)
{
    const float* A = Wq2; float* C = Cq;
    if (blockIdx.z == 1) { A = Wk2; C = Ck; }
    else if (blockIdx.z == 2) { A = Wv2; C = Cv; }
    sgemm_body(A, Wo1T, zeros, C, 0, blockIdx.y*128, blockIdx.x*128);
}

// ======================= 512x512 transpose ==================================
__global__ __launch_bounds__(256) void transpose512_kernel(
    const float* __restrict__ in, float* __restrict__ out)
{
    __shared__ float t[32][33];
    const int tx = threadIdx.x, ty = threadIdx.y;   // (32, 8)
    const int x0 = blockIdx.x*32, y0 = blockIdx.y*32;
#pragma unroll
    for (int r = 0; r < 4; r++)
        t[ty*4+r][tx] = in[(size_t)(y0 + ty*4 + r)*512 + x0 + tx];
    __syncthreads();
#pragma unroll
    for (int r = 0; r < 4; r++)
        out[(size_t)(x0 + ty*4 + r)*512 + y0 + tx] = t[tx][ty*4+r];
}

// ======================= bias fusion + zeros ================================
// b'_z[i] = sum_m Wz[i][m]*bo1[m] + bz[i];  also zeroes the zeros[] array.
__global__ __launch_bounds__(256) void biasfuse_kernel(
    const float* __restrict__ Wq2, const float* __restrict__ Wk2,
    const float* __restrict__ Wv2, const float* __restrict__ bo1,
    const float* __restrict__ bq2, const float* __restrict__ bk2,
    const float* __restrict__ bv2,
    float* __restrict__ bpq, float* __restrict__ bpk, float* __restrict__ bpv,
    float* __restrict__ zeros)
{
    const int z = blockIdx.x;
    const float* W = (z == 0) ? Wq2 : (z == 1) ? Wk2 : Wv2;
    const float* bi = (z == 0) ? bq2 : (z == 1) ? bk2 : bv2;
    float* bo = (z == 0) ? bpq : (z == 1) ? bpk : bpv;
    const int wid = threadIdx.x >> 5, lane = threadIdx.x & 31;

    if (z == 0) { zeros[threadIdx.x] = 0.f; zeros[threadIdx.x + 256] = 0.f; }

    for (int i = wid; i < 512; i += 8) {
        const float* row = W + (size_t)i * 512;
        float s = 0.f;
#pragma unroll
        for (int seg = 0; seg < 16; seg++)
            s += row[lane + seg*32] * bo1[lane + seg*32];
#pragma unroll
        for (int o = 16; o; o >>= 1)
            s += __shfl_xor_sync(0xffffffffu, s, o);
        if (lane == 0) bo[i] = s + bi[i];
    }
}

// ======================= top-5 insertion helper =============================
__device__ __forceinline__ void ins5(float (&v)[5], int (&ix)[5], float sv, int id)
{
    if (sv > v[4]) {
        if (sv > v[0]) {
            v[4]=v[3]; ix[4]=ix[3]; v[3]=v[2]; ix[3]=ix[2];
            v[2]=v[1]; ix[2]=ix[1]; v[1]=v[0]; ix[1]=ix[0];
            v[0]=sv; ix[0]=id;
        } else if (sv > v[1]) {
            v[4]=v[3]; ix[4]=ix[3]; v[3]=v[2]; ix[3]=ix[2];
            v[2]=v[1]; ix[2]=ix[1]; v[1]=sv; ix[1]=id;
        } else if (sv > v[2]) {
            v[4]=v[3]; ix[4]=ix[3]; v[3]=v[2]; ix[3]=ix[2];
            v[2]=sv; ix[2]=id;
        } else if (sv > v[3]) {
            v[4]=v[3]; ix[4]=ix[3]; v[3]=sv; ix[3]=id;
        } else {
            v[4]=sv; ix[4]=id;
        }
    }
}

// ======================= Stage-1: top-5 local attention =====================
#define LOC_SMEM_FLOATS (32*129 + 128*129 + 32*5 + 32*5)
#define LOC_SMEM_BYTES  (LOC_SMEM_FLOATS*4)

__global__ __launch_bounds__(256) void local_attn_kernel(
    const float* __restrict__ Q, const float* __restrict__ K,
    const float* __restrict__ V, float* __restrict__ out)
{
    extern __shared__ float sm[];
    float* Qs = sm;
    float* Ks = Qs + 32*129;
    float* w5 = Ks + 128*129;
    int*   i5 = (int*)(w5 + 32*5);
    float* cvals = Ks;
    int*   cidx  = (int*)(Ks + 32*160);

    const int tid = threadIdx.x;
    const int b = blockIdx.z, h = blockIdx.y;
    const int q0 = blockIdx.x * 32;
    const float* Qb = Q + (size_t)((b*Hh + h)*Cc) * Dk;
    const float* Kb = K + (size_t)((b*Hh + h)*Cc) * Dk;
    const float* Vb = V + (size_t)((b*Hh + h)*Cc) * Dk;

    for (int t = tid; t < 32*32; t += 256) {
        int row = t >> 5, seg = t & 31;
        float4 v = ((const float4*)(Qb + (size_t)(q0 + row)*Dk))[seg];
        float* p = Qs + row*129 + seg*4;
        p[0]=v.x; p[1]=v.y; p[2]=v.z; p[3]=v.w;
    }

    const int qg = tid >> 5;
    const int lane = tid & 31;
    const float scl = 0.08838834764831845f;

    float tv[4][5]; int ti[4][5];
#pragma unroll
    for (int r = 0; r < 4; r++)
#pragma unroll
        for (int j = 0; j < 5; j++) { tv[r][j] = -1e30f; ti[r][j] = 0; }

    for (int ch = 0; ch < 4; ch++) {
        const int e0 = ch * 128;
        for (int t = tid; t < 128*32; t += 256) {
            int row = t >> 5, seg = t & 31;
            float4 v = ((const float4*)(Kb + (size_t)(e0 + row)*Dk))[seg];
            float* p = Ks + row*129 + seg*4;
            p[0]=v.x; p[1]=v.y; p[2]=v.z; p[3]=v.w;
        }
        __syncthreads();

        float a[4][4];
#pragma unroll
        for (int r = 0; r < 4; r++)
#pragma unroll
            for (int j = 0; j < 4; j++) a[r][j] = 0.f;

        const float* qp  = Qs + (qg*4)*129;
        const float* kp0 = Ks + lane*129;
        const float* kp1 = kp0 + 32*129;
        const float* kp2 = kp0 + 64*129;
        const float* kp3 = kp0 + 96*129;
#pragma unroll 4
        for (int k = 0; k < 128; k++) {
            float qv0 = qp[k], qv1 = qp[129+k], qv2 = qp[258+k], qv3 = qp[387+k];
            float kv0 = kp0[k], kv1 = kp1[k], kv2 = kp2[k], kv3 = kp3[k];
            a[0][0]+=qv0*kv0; a[0][1]+=qv0*kv1; a[0][2]+=qv0*kv2; a[0][3]+=qv0*kv3;
            a[1][0]+=qv1*kv0; a[1][1]+=qv1*kv1; a[1][2]+=qv1*kv2; a[1][3]+=qv1*kv3;
            a[2][0]+=qv2*kv0; a[2][1]+=qv2*kv1; a[2][2]+=qv2*kv2; a[2][3]+=qv2*kv3;
            a[3][0]+=qv3*kv0; a[3][1]+=qv3*kv1; a[3][2]+=qv3*kv2; a[3][3]+=qv3*kv3;
        }
#pragma unroll
        for (int r = 0; r < 4; r++)
#pragma unroll
            for (int j = 0; j < 4; j++)
                ins5(tv[r], ti[r], a[r][j]*scl, e0 + lane + 32*j);
        __syncthreads();
    }

#pragma unroll
    for (int r = 0; r < 4; r++) {
        int row = qg*4 + r;
#pragma unroll
        for (int j = 0; j < 5; j++) {
            cvals[row*160 + lane*5 + j] = tv[r][j];
            cidx [row*160 + lane*5 + j] = ti[r][j];
        }
    }
    __syncthreads();

    if (tid < 32) {
        float v[5]; int ix[5];
#pragma unroll
        for (int j = 0; j < 5; j++) { v[j] = -1e30f; ix[j] = 0; }
        const float* cv = cvals + tid*160;
        const int*   ci = cidx  + tid*160;
        for (int j = 0; j < 160; j++) ins5(v, ix, cv[j], ci[j]);
        float m = v[0];
        float w0 = 1.f;
        float w1 = __expf(v[1]-m), w2 = __expf(v[2]-m);
        float w3 = __expf(v[3]-m), w4 = __expf(v[4]-m);
        float inv = 1.f / (w0+w1+w2+w3+w4);
        w5[tid*5+0]=w0*inv; w5[tid*5+1]=w1*inv; w5[tid*5+2]=w2*inv;
        w5[tid*5+3]=w3*inv; w5[tid*5+4]=w4*inv;
        i5[tid*5+0]=ix[0]; i5[tid*5+1]=ix[1]; i5[tid*5+2]=ix[2];
        i5[tid*5+3]=ix[3]; i5[tid*5+4]=ix[4];
    }
    __syncthreads();

    const int q  = tid >> 3;
    const int d0 = (tid & 7) * 16;
    float acc[16];
#pragma unroll
    for (int t = 0; t < 16; t++) acc[t] = 0.f;
#pragma unroll
    for (int j = 0; j < 5; j++) {
        float w = w5[q*5+j];
        int   e = i5[q*5+j];
        const float4* vr = (const float4*)(Vb + (size_t)e*Dk + d0);
#pragma unroll
        for (int t = 0; t < 4; t++) {
            float4 v = vr[t];
            acc[t*4+0] += w*v.x; acc[t*4+1] += w*v.y;
            acc[t*4+2] += w*v.z; acc[t*4+3] += w*v.w;
        }
    }
    float* op = out + (size_t)(b*Cc + q0 + q)*Ff + h*Dk + d0;
#pragma unroll
    for (int t = 0; t < 4; t++)
        ((float4*)op)[t] = make_float4(acc[t*4+0],acc[t*4+1],acc[t*4+2],acc[t*4+3]);
}

// ======================= Stage-2: flash global attention ====================
#define GLB_SMEM_FLOATS (32*129 + 128*129 + 32*132)
#define GLB_SMEM_BYTES  (GLB_SMEM_FLOATS*4)

__global__ __launch_bounds__(256) void global_attn_kernel(
    const float* __restrict__ Q, const float* __restrict__ K,
    const float* __restrict__ V, float* __restrict__ out)
{
    extern __shared__ float sm[];
    float* Qs = sm;
    float* KV = Qs + 32*129;
    float* sw = KV + 128*129;

    const int tid = threadIdx.x;
    const int b = blockIdx.z, h = blockIdx.y;
    const int q0 = blockIdx.x * 32;
    const float* Qb = Q + (size_t)((b*Hh + h)*Cc) * Dk;
    const float* Kb = K + (size_t)((b*Hh + h)*Cc) * Dk;
    const float* Vb = V + (size_t)((b*Hh + h)*Cc) * Dk;

    for (int t = tid; t < 32*32; t += 256) {
        int row = t >> 5, seg = t & 31;
        float4 v = ((const float4*)(Qb + (size_t)(q0 + row)*Dk))[seg];
        float* p = Qs + row*129 + seg*4;
        p[0]=v.x; p[1]=v.y; p[2]=v.z; p[3]=v.w;
    }

    const int qg = tid >> 5;
    const int lane = tid & 31;
    const float scl = 0.08838834764831845f;

    float acc[4][4];
    float mrun[4], lrun[4];
#pragma unroll
    for (int r = 0; r < 4; r++) {
        mrun[r] = -1e30f; lrun[r] = 0.f;
#pragma unroll
        for (int j = 0; j < 4; j++) acc[r][j] = 0.f;
    }

    for (int ch = 0; ch < 4; ch++) {
        const int e0 = ch * 128;
        for (int t = tid; t < 128*32; t += 256) {
            int row = t >> 5, seg = t & 31;
            float4 v = ((const float4*)(Kb + (size_t)(e0 + row)*Dk))[seg];
            float* p = KV + row*129 + seg*4;
            p[0]=v.x; p[1]=v.y; p[2]=v.z; p[3]=v.w;
        }
        __syncthreads();

        float a[4][4];
#pragma unroll
        for (int r = 0; r < 4; r++)
#pragma unroll
            for (int j = 0; j < 4; j++) a[r][j] = 0.f;

        const float* qp  = Qs + (qg*4)*129;
        const float* kp0 = KV + lane*129;
        const float* kp1 = kp0 + 32*129;
        const float* kp2 = kp0 + 64*129;
        const float* kp3 = kp0 + 96*129;
#pragma unroll 4
        for (int k = 0; k < 128; k++) {
            float qv0 = qp[k], qv1 = qp[129+k], qv2 = qp[258+k], qv3 = qp[387+k];
            float kv0 = kp0[k], kv1 = kp1[k], kv2 = kp2[k], kv3 = kp3[k];
            a[0][0]+=qv0*kv0; a[0][1]+=qv0*kv1; a[0][2]+=qv0*kv2; a[0][3]+=qv0*kv3;
            a[1][0]+=qv1*kv0; a[1][1]+=qv1*kv1; a[1][2]+=qv1*kv2; a[1][3]+=qv1*kv3;
            a[2][0]+=qv2*kv0; a[2][1]+=qv2*kv1; a[2][2]+=qv2*kv2; a[2][3]+=qv2*kv3;
            a[3][0]+=qv3*kv0; a[3][1]+=qv3*kv1; a[3][2]+=qv3*kv2; a[3][3]+=qv3*kv3;
        }

#pragma unroll
        for (int r = 0; r < 4; r++) {
            float s0 = a[r][0]*scl, s1 = a[r][1]*scl, s2 = a[r][2]*scl, s3 = a[r][3]*scl;
            float cm = fmaxf(fmaxf(s0,s1), fmaxf(s2,s3));
#pragma unroll
            for (int o = 16; o; o >>= 1)
                cm = fmaxf(cm, __shfl_xor_sync(0xffffffffu, cm, o));
            float mnew = fmaxf(mrun[r], cm);
            float corr = __expf(mrun[r] - mnew);
            float p0 = __expf(s0 - mnew), p1 = __expf(s1 - mnew);
            float p2 = __expf(s2 - mnew), p3 = __expf(s3 - mnew);
            float ps = p0+p1+p2+p3;
#pragma unroll
            for (int o = 16; o; o >>= 1)
                ps += __shfl_xor_sync(0xffffffffu, ps, o);
            lrun[r] = lrun[r]*corr + ps;
            mrun[r] = mnew;
            acc[r][0]*=corr; acc[r][1]*=corr; acc[r][2]*=corr; acc[r][3]*=corr;
            float* swr = sw + (qg*4 + r)*132;
            swr[lane]      = p0;
            swr[lane + 32] = p1;
            swr[lane + 64] = p2;
            swr[lane + 96] = p3;
        }
        __syncthreads();

        for (int t = tid; t < 128*32; t += 256) {
            int row = t >> 5, seg = t & 31;
            float4 v = ((const float4*)(Vb + (size_t)(e0 + row)*Dk))[seg];
            float* p = KV + row*129 + seg*4;
            p[0]=v.x; p[1]=v.y; p[2]=v.z; p[3]=v.w;
        }
        __syncthreads();

        {
            const float* swr0 = sw + (qg*4+0)*132;
            const float* swr1 = sw + (qg*4+1)*132;
            const float* swr2 = sw + (qg*4+2)*132;
            const float* swr3 = sw + (qg*4+3)*132;
#pragma unroll 8
            for (int e = 0; e < 128; e++) {
                float w0 = swr0[e], w1 = swr1[e], w2 = swr2[e], w3 = swr3[e];
                const float* vp = KV + e*129 + lane;
                float v0 = vp[0], v1 = vp[32], v2 = vp[64], v3 = vp[96];
                acc[0][0]+=w0*v0; acc[0][1]+=w0*v1; acc[0][2]+=w0*v2; acc[0][3]+=w0*v3;
                acc[1][0]+=w1*v0; acc[1][1]+=w1*v1; acc[1][2]+=w1*v2; acc[1][3]+=w1*v3;
                acc[2][0]+=w2*v0; acc[2][1]+=w2*v1; acc[2][2]+=w2*v2; acc[2][3]+=w2*v3;
                acc[3][0]+=w3*v0; acc[3][1]+=w3*v1; acc[3][2]+=w3*v2; acc[3][3]+=w3*v3;
            }
        }
        __syncthreads();
    }

#pragma unroll
    for (int r = 0; r < 4; r++) {
        float inv = 1.f / lrun[r];
        int row = q0 + qg*4 + r;
        float* base = out + (size_t)(b*Cc + row)*Ff + h*Dk;
        base[lane]      = acc[r][0]*inv;
        base[lane + 32] = acc[r][1]*inv;
        base[lane + 64] = acc[r][2]*inv;
        base[lane + 96] = acc[r][3]*inv;
    }
}

// ======================= residual + LayerNorm ===============================
__global__ __launch_bounds__(128) void resid_ln_kernel(
    const float* __restrict__ x, const float* __restrict__ gl,
    const float* __restrict__ gamma, const float* __restrict__ beta,
    float* __restrict__ out)
{
    __shared__ float s1[4], s2[4];
    const int row = blockIdx.x, tid = threadIdx.x;
    const float4 xv = ((const float4*)(x  + (size_t)row*Ff))[tid];
    const float4 gv = ((const float4*)(gl + (size_t)row*Ff))[tid];
    float h0 = xv.x+gv.x, h1 = xv.y+gv.y, h2 = xv.z+gv.z, h3 = xv.w+gv.w;
    float s = h0+h1+h2+h3;
    float q = h0*h0+h1*h1+h2*h2+h3*h3;
#pragma unroll
    for (int o = 16; o; o >>= 1) {
        s += __shfl_xor_sync(0xffffffffu, s, o);
        q += __shfl_xor_sync(0xffffffffu, q, o);
    }
    int w = tid >> 5;
    if ((tid & 31) == 0) { s1[w] = s; s2[w] = q; }
    __syncthreads();
    float ts = s1[0]+s1[1]+s1[2]+s1[3];
    float tq = s2[0]+s2[1]+s2[2]+s2[3];
    float mean = ts * (1.f/512.f);
    float var  = tq * (1.f/512.f) - mean*mean;
    float inv  = rsqrtf(var + 1e-5f);
    const float4 gm = ((const float4*)gamma)[tid];
    const float4 bt = ((const float4*)beta)[tid];
    float4 o;
    o.x = (h0-mean)*inv*gm.x + bt.x;
    o.y = (h1-mean)*inv*gm.y + bt.y;
    o.z = (h2-mean)*inv*gm.z + bt.z;
    o.w = (h3-mean)*inv*gm.w + bt.w;
    ((float4*)(out + (size_t)row*Ff))[tid] = o;
}

// ============================================================================
extern "C" void kernel_launch(void* const* d_in, const int* in_sizes, int n_in,
                              void* d_out, int out_size)
{
    const float* x    = (const float*)d_in[0];
    const float* Wq1  = (const float*)d_in[1];
    const float* bq1  = (const float*)d_in[2];
    const float* Wk1  = (const float*)d_in[3];
    const float* bk1  = (const float*)d_in[4];
    const float* Wv1  = (const float*)d_in[5];
    const float* bv1  = (const float*)d_in[6];
    const float* Wo1  = (const float*)d_in[7];
    const float* bo1  = (const float*)d_in[8];
    const float* Wq2  = (const float*)d_in[9];
    const float* bq2  = (const float*)d_in[10];
    const float* Wk2  = (const float*)d_in[11];
    const float* bk2  = (const float*)d_in[12];
    const float* Wv2  = (const float*)d_in[13];
    const float* bv2  = (const float*)d_in[14];
    const float* Wo2  = (const float*)d_in[15];
    const float* bo2  = (const float*)d_in[16];
    const float* gamma= (const float*)d_in[17];
    const float* beta = (const float*)d_in[18];
    float* out = (float*)d_out;

    float *Qp, *Kp, *Vp, *attp, *globp, *wo1t, *wfused, *bfused;
    cudaGetSymbolAddress((void**)&Qp,     g_Q);
    cudaGetSymbolAddress((void**)&Kp,     g_K);
    cudaGetSymbolAddress((void**)&Vp,     g_V);
    cudaGetSymbolAddress((void**)&attp,   g_att);
    cudaGetSymbolAddress((void**)&globp,  g_glob);
    cudaGetSymbolAddress((void**)&wo1t,   g_scr1);
    cudaGetSymbolAddress((void**)&wfused, g_scr2);
    cudaGetSymbolAddress((void**)&bfused, g_scr3);

    float* Wpq = wfused;
    float* Wpk = wfused + Ff*Ff;
    float* Wpv = wfused + 2*Ff*Ff;
    float* bpq = bfused;
    float* bpk = bfused + Ff;
    float* bpv = bfused + 2*Ff;
    float* zeros = bfused + 3*Ff;

    cudaFuncSetAttribute(local_attn_kernel,
        cudaFuncAttributeMaxDynamicSharedMemorySize, LOC_SMEM_BYTES);
    cudaFuncSetAttribute(global_attn_kernel,
        cudaFuncAttributeMaxDynamicSharedMemorySize, GLB_SMEM_BYTES);

    dim3 ggrid(4, 128);
    dim3 qkvgrid(4, 128, 3);
    dim3 fusegrid(4, 4, 3);
    dim3 tgrid(16, 16);
    dim3 tblk(32, 8);
    dim3 agrid(16, 4, 32);

    // ---- per-call prep: fold O1 into stage-2 projections ----
    transpose512_kernel<<<tgrid, tblk>>>(Wo1, wo1t);
    biasfuse_kernel<<<3, 256>>>(Wq2, Wk2, Wv2, bo1, bq2, bk2, bv2,
                                bpq, bpk, bpv, zeros);
    sgemm_fuse_kernel<<<fusegrid, 256>>>(Wq2, Wk2, Wv2, wo1t, zeros,
                                         Wpq, Wpk, Wpv);

    // Stage 1: fused Q/K/V projections (head-split)
    sgemm_qkv_kernel<<<qkvgrid, 256>>>(x, Wq1, bq1, Qp, Wk1, bk1, Kp, Wv1, bv1, Vp);
    // Top-5 local attention -> merged layout (att1)
    local_attn_kernel<<<agrid, 256, LOC_SMEM_BYTES>>>(Qp, Kp, Vp, attp);
    // Stage 2: fused projections directly on att1 (O1 eliminated)
    sgemm_qkv_kernel<<<qkvgrid, 256>>>(attp, Wpq, bpq, Qp, Wpk, bpk, Kp, Wpv, bpv, Vp);
    // Dense global attention (flash online softmax)
    global_attn_kernel<<<agrid, 256, GLB_SMEM_BYTES>>>(Qp, Kp, Vp, attp);
    // Output projection
    sgemm_nt_kernel<<<ggrid, 256>>>(attp, Wo2, bo2, globp, 0);
    // Residual + LayerNorm -> final output
    resid_ln_kernel<<<NTOK, 128>>>(x, globp, gamma, beta, out);
}